// round 7
// baseline (speedup 1.0000x reference)
#include <cuda_runtime.h>
#include <cuda_bf16.h>
#include <stdint.h>
#include <math.h>

#define B_DIM 8
#define C_DIM 256
#define H_DIM 128
#define W_DIM 128
#define HW    (H_DIM * W_DIM)
#define NTOK  (B_DIM * HW)
#define QK_SCALE 0.0625f

// q/k/v bf16 hi/lo split, [token][channel]
__device__ __nv_bfloat16 g_qhi[NTOK * C_DIM];
__device__ __nv_bfloat16 g_qlo[NTOK * C_DIM];
__device__ __nv_bfloat16 g_khi[NTOK * C_DIM];
__device__ __nv_bfloat16 g_klo[NTOK * C_DIM];
__device__ __nv_bfloat16 g_vhi[NTOK * C_DIM];
__device__ __nv_bfloat16 g_vlo[NTOK * C_DIM];
// X in c-major bf16 split: [c][token]
__device__ __nv_bfloat16 g_xhi[C_DIM * NTOK];
__device__ __nv_bfloat16 g_xlo[C_DIM * NTOK];
// Weights split: [mat][o][c]
__device__ __nv_bfloat16 g_whi[3 * C_DIM * C_DIM];
__device__ __nv_bfloat16 g_wlo[3 * C_DIM * C_DIM];

__device__ __forceinline__ uint32_t smem_u32(const void* p) {
    uint32_t a;
    asm("{ .reg .u64 t; cvta.to.shared.u64 t, %1; cvt.u32.u64 %0, t; }" : "=r"(a) : "l"(p));
    return a;
}
__device__ __forceinline__ void cp16(uint32_t dst, const void* src) {
    asm volatile("cp.async.cg.shared.global [%0], [%1], 16;" :: "r"(dst), "l"(src));
}
__device__ __forceinline__ void cp_commit() { asm volatile("cp.async.commit_group;" ::: "memory"); }
__device__ __forceinline__ void cp_wait1()  { asm volatile("cp.async.wait_group 1;" ::: "memory"); }
__device__ __forceinline__ void cp_wait0()  { asm volatile("cp.async.wait_group 0;" ::: "memory"); }

__device__ __forceinline__ void ldm_x4(uint32_t& r0, uint32_t& r1, uint32_t& r2, uint32_t& r3, uint32_t addr) {
    asm volatile("ldmatrix.sync.aligned.m8n8.x4.shared.b16 {%0,%1,%2,%3}, [%4];"
                 : "=r"(r0), "=r"(r1), "=r"(r2), "=r"(r3) : "r"(addr));
}
__device__ __forceinline__ void ldm_x4_t(uint32_t& r0, uint32_t& r1, uint32_t& r2, uint32_t& r3, uint32_t addr) {
    asm volatile("ldmatrix.sync.aligned.m8n8.x4.trans.shared.b16 {%0,%1,%2,%3}, [%4];"
                 : "=r"(r0), "=r"(r1), "=r"(r2), "=r"(r3) : "r"(addr));
}
__device__ __forceinline__ void mma16816(float* c, const uint32_t* a, uint32_t b0, uint32_t b1) {
    asm volatile("mma.sync.aligned.m16n8k16.row.col.f32.bf16.bf16.f32 "
                 "{%0,%1,%2,%3},{%4,%5,%6,%7},{%8,%9},{%0,%1,%2,%3};"
                 : "+f"(c[0]), "+f"(c[1]), "+f"(c[2]), "+f"(c[3])
                 : "r"(a[0]), "r"(a[1]), "r"(a[2]), "r"(a[3]), "r"(b0), "r"(b1));
}
__device__ __forceinline__ uint32_t pk_hi(float x, float y) {
    __nv_bfloat162 t = __floats2bfloat162_rn(x, y);
    return *(uint32_t*)&t;
}
__device__ __forceinline__ uint32_t pk_lo(float x, float y) {
    float xh = __bfloat162float(__float2bfloat16(x));
    float yh = __bfloat162float(__float2bfloat16(y));
    __nv_bfloat162 t = __floats2bfloat162_rn(x - xh, y - yh);
    return *(uint32_t*)&t;
}

__global__ __launch_bounds__(256)
void wconvert(const float* __restrict__ wq, const float* __restrict__ wk,
              const float* __restrict__ wv)
{
    int idx = blockIdx.x * 256 + threadIdx.x;
    int mat = idx >> 16, r = idx & 65535;
    const float* src = (mat == 0) ? wq : (mat == 1) ? wk : wv;
    float v = src[r];
    __nv_bfloat16 hi = __float2bfloat16(v);
    g_whi[idx] = hi;
    g_wlo[idx] = __float2bfloat16(v - __bfloat162float(hi));
}

// Coalesced X conversion: a NCHW fp32 -> c-major [c][token] bf16 hi/lo
__global__ __launch_bounds__(256)
void xconvert(const float* __restrict__ a)
{
    int idx4 = blockIdx.x * 256 + threadIdx.x;
    int b    = idx4 >> 20;
    int rem  = idx4 & 1048575;
    int c    = rem >> 12;
    int hw4  = rem & 4095;
    float4 v = *(const float4*)(a + (size_t)idx4 * 4);
    size_t o = (size_t)c * NTOK + (size_t)b * HW + (size_t)hw4 * 4;
    float hx = __bfloat162float(__float2bfloat16(v.x));
    float hy = __bfloat162float(__float2bfloat16(v.y));
    float hz = __bfloat162float(__float2bfloat16(v.z));
    float hw = __bfloat162float(__float2bfloat16(v.w));
    __nv_bfloat162* ph = (__nv_bfloat162*)(g_xhi + o);
    ph[0] = __floats2bfloat162_rn(v.x, v.y);
    ph[1] = __floats2bfloat162_rn(v.z, v.w);
    __nv_bfloat162* pl = (__nv_bfloat162*)(g_xlo + o);
    pl[0] = __floats2bfloat162_rn(v.x - hx, v.y - hy);
    pl[1] = __floats2bfloat162_rn(v.z - hz, v.w - hw);
}

// ===========================================================================
// QKV GEMM v2: 8 chunk-iterations. it<4: {Xhi(kc), Whi(kc), Wlo(kc)} -> 2
// passes per kstep. it>=4: {Xlo(kc), Whi(kc)} -> 1 pass. Double-buffered.
// Stage: A 16KB @0, Bhi 16KB @16384, Blo 16KB @32768 (stride 49152).
// ===========================================================================
#define QKV_STAGE 49152
#define QKV_SMEM  (2 * QKV_STAGE)

__global__ __launch_bounds__(256, 2)
void qkv_mma(const float* __restrict__ bq, const float* __restrict__ bk,
             const float* __restrict__ bv)
{
    extern __shared__ char smem[];
    const uint32_t sb = smem_u32(smem);
    const int tid = threadIdx.x, lane = tid & 31, wid = tid >> 5;
    const int wm0 = (wid & 3) * 32;
    const int wn0 = (wid >> 2) * 64;
    const int mat  = blockIdx.x >> 1;
    const int half = blockIdx.x & 1;
    const int tok0 = blockIdx.y * 128;

    const __nv_bfloat16* xhiB = g_xhi + tok0;
    const __nv_bfloat16* xloB = g_xlo + tok0;
    const __nv_bfloat16* whiB = g_whi + mat * 65536 + half * 32768;
    const __nv_bfloat16* wloB = g_wlo + mat * 65536 + half * 32768;

    // loader for iteration it (0..7), stage stg
    const int lrowA = tid >> 4, lc16A = tid & 15;        // A: 4 iters x (16 rows)
    const int lrowB = tid >> 3, lc16B = tid & 7;         // B: 4 iters x (32 rows)

    auto loadIt = [&](int stg, int it) {
        const uint32_t st = sb + stg * QKV_STAGE;
        const int kc = it & 3;
        const __nv_bfloat16* As = (it < 4) ? (xhiB + (size_t)(kc * 64) * NTOK)
                                           : (xloB + (size_t)(kc * 64) * NTOK);
        #pragma unroll
        for (int r = 0; r < 4; ++r) {
            int row = r * 16 + lrowA;
            cp16(st + row * 256 + ((lc16A ^ (row & 7)) << 4),
                 As + (size_t)row * NTOK + lc16A * 8);
        }
        const __nv_bfloat16* Bh = whiB + kc * 64;
        #pragma unroll
        for (int r = 0; r < 4; ++r) {
            int row = r * 32 + lrowB;
            cp16(st + 16384 + row * 128 + ((lc16B ^ (row & 7)) << 4),
                 Bh + row * 256 + lc16B * 8);
        }
        if (it < 4) {
            const __nv_bfloat16* Bl = wloB + kc * 64;
            #pragma unroll
            for (int r = 0; r < 4; ++r) {
                int row = r * 32 + lrowB;
                cp16(st + 32768 + row * 128 + ((lc16B ^ (row & 7)) << 4),
                     Bl + row * 256 + lc16B * 8);
            }
        }
    };

    float acc[2][8][4];
    #pragma unroll
    for (int mt = 0; mt < 2; ++mt)
        #pragma unroll
        for (int n8 = 0; n8 < 8; ++n8)
            #pragma unroll
            for (int e = 0; e < 4; ++e) acc[mt][n8][e] = 0.0f;

    loadIt(0, 0); cp_commit();

    for (int it = 0; it < 8; ++it) {
        if (it < 7) { loadIt((it + 1) & 1, it + 1); cp_commit(); cp_wait1(); }
        else cp_wait0();
        __syncthreads();
        const uint32_t st = sb + (it & 1) * QKV_STAGE;
        const int two = (it < 4);

        #pragma unroll
        for (int ks = 0; ks < 4; ++ks) {
            uint32_t af[2][4];
            const int arow = ks * 16 + (lane & 7) + ((lane >> 4) << 3);
            #pragma unroll
            for (int mt = 0; mt < 2; ++mt) {
                int chunk = (wm0 >> 3) + mt * 2 + ((lane >> 3) & 1);
                uint32_t addr = st + arow * 256 + ((chunk ^ (arow & 7)) << 4);
                ldm_x4_t(af[mt][0], af[mt][1], af[mt][2], af[mt][3], addr);
            }
            const int rbase = (lane & 7) + ((lane >> 3) & 1) * 8;
            const int c16 = ks * 2 + (lane >> 4);
            #pragma unroll
            for (int ng = 0; ng < 4; ++ng) {
                int brow = wn0 + ng * 16 + rbase;
                uint32_t bsw = brow * 128 + ((c16 ^ (brow & 7)) << 4);
                uint32_t b0, b1, b2, b3;
                ldm_x4(b0, b1, b2, b3, st + 16384 + bsw);
                #pragma unroll
                for (int mt = 0; mt < 2; ++mt) {
                    mma16816(acc[mt][2 * ng],     af[mt], b0, b2);
                    mma16816(acc[mt][2 * ng + 1], af[mt], b1, b3);
                }
                if (two) {
                    ldm_x4(b0, b1, b2, b3, st + 32768 + bsw);
                    #pragma unroll
                    for (int mt = 0; mt < 2; ++mt) {
                        mma16816(acc[mt][2 * ng],     af[mt], b0, b2);
                        mma16816(acc[mt][2 * ng + 1], af[mt], b1, b3);
                    }
                }
            }
        }
        __syncthreads();
    }

    const float* bias = (mat == 0) ? bq : (mat == 1) ? bk : bv;
    const float scale = (mat == 0) ? QK_SCALE : 1.0f;
    __nv_bfloat16* dhi = (mat == 0) ? g_qhi : (mat == 1) ? g_khi : g_vhi;
    __nv_bfloat16* dlo = (mat == 0) ? g_qlo : (mat == 1) ? g_klo : g_vlo;

    const int g = lane >> 2, t = lane & 3;
    #pragma unroll
    for (int mt = 0; mt < 2; ++mt) {
        size_t r0 = (size_t)(tok0 + wm0 + mt * 16 + g), r1 = r0 + 8;
        #pragma unroll
        for (int n8 = 0; n8 < 8; ++n8) {
            int o = half * 128 + wn0 + n8 * 8 + t * 2;
            float b0v = bias[o], b1v = bias[o + 1];
            float v00 = (acc[mt][n8][0] + b0v) * scale;
            float v01 = (acc[mt][n8][1] + b1v) * scale;
            float v10 = (acc[mt][n8][2] + b0v) * scale;
            float v11 = (acc[mt][n8][3] + b1v) * scale;
            *(uint32_t*)(dhi + r0 * 256 + o) = pk_hi(v00, v01);
            *(uint32_t*)(dlo + r0 * 256 + o) = pk_lo(v00, v01);
            *(uint32_t*)(dhi + r1 * 256 + o) = pk_hi(v10, v11);
            *(uint32_t*)(dlo + r1 * 256 + o) = pk_lo(v10, v11);
        }
    }
}

// ===========================================================================
// HMMA attention v2: single-buffered chunks, 65KB smem, <=128 regs,
// 2 CTAs/SM. Layout: S chunk {qhi,qlo,khi,klo} 4x16KB @0; V chunk {vhi,vlo}
// 2x16KB @0; Os fp32 [128][66] @32768.
// ===========================================================================
#define ATTN_SMEM 66560

__global__ __launch_bounds__(256, 2)
void attn_mma(const float* __restrict__ a, const float* __restrict__ Wp,
              float* __restrict__ out)
{
    extern __shared__ char smem[];
    const uint32_t sb = smem_u32(smem);
    float* Os = (float*)(smem + 32768);
    const int tid = threadIdx.x, lane = tid & 31, wid = tid >> 5;
    const int m0 = wid * 16;
    const int bh = blockIdx.x, b = bh >> 7, h = bh & 127;
    const size_t tokbase = (size_t)bh * 128;

    const int lrow = tid >> 3, lc16 = tid & 7;

    auto loadQK = [&](int kc) {
        const size_t scol = tokbase * 256 + kc * 64;
        #pragma unroll
        for (int r = 0; r < 4; ++r) {
            int row = r * 32 + lrow;
            uint32_t doff = row * 128 + ((lc16 ^ (row & 7)) << 4);
            size_t soff = scol + (size_t)row * 256 + lc16 * 8;
            cp16(sb + 0     + doff, g_qhi + soff);
            cp16(sb + 16384 + doff, g_qlo + soff);
            cp16(sb + 32768 + doff, g_khi + soff);
            cp16(sb + 49152 + doff, g_klo + soff);
        }
    };
    auto loadV = [&](int cc) {
        const size_t scol = tokbase * 256 + cc * 64;
        #pragma unroll
        for (int r = 0; r < 4; ++r) {
            int row = r * 32 + lrow;
            uint32_t doff = row * 128 + ((lc16 ^ (row & 7)) << 4);
            size_t soff = scol + (size_t)row * 256 + lc16 * 8;
            cp16(sb + 0     + doff, g_vhi + soff);
            cp16(sb + 16384 + doff, g_vlo + soff);
        }
    };

    float sacc[16][4];
    #pragma unroll
    for (int j = 0; j < 16; ++j)
        #pragma unroll
        for (int e = 0; e < 4; ++e) sacc[j][e] = 0.0f;

    loadQK(0); cp_commit();
    for (int kc = 0; kc < 4; ++kc) {
        cp_wait0();
        __syncthreads();
        #pragma unroll
        for (int ks = 0; ks < 4; ++ks) {
            uint32_t ah[4], al[4];
            const int c16 = ks * 2 + (lane >> 4);
            int arow = m0 + (lane & 15);
            uint32_t aoff = arow * 128 + ((c16 ^ (arow & 7)) << 4);
            ldm_x4(ah[0], ah[1], ah[2], ah[3], sb + aoff);
            ldm_x4(al[0], al[1], al[2], al[3], sb + 16384 + aoff);
            #pragma unroll
            for (int bn = 0; bn < 8; ++bn) {
                int brow = bn * 16 + (lane & 15);
                uint32_t boff = brow * 128 + ((c16 ^ (brow & 7)) << 4);
                uint32_t b0, b1, b2, b3;
                ldm_x4(b0, b1, b2, b3, sb + 32768 + boff);
                mma16816(sacc[2 * bn],     ah, b0, b2);
                mma16816(sacc[2 * bn + 1], ah, b1, b3);
                mma16816(sacc[2 * bn],     al, b0, b2);
                mma16816(sacc[2 * bn + 1], al, b1, b3);
                ldm_x4(b0, b1, b2, b3, sb + 49152 + boff);
                mma16816(sacc[2 * bn],     ah, b0, b2);
                mma16816(sacc[2 * bn + 1], ah, b1, b3);
            }
        }
        __syncthreads();
        if (kc < 3) { loadQK(kc + 1); cp_commit(); }
    }
    loadV(0); cp_commit();

    float mx0 = -1e30f, mx1 = -1e30f;
    #pragma unroll
    for (int j = 0; j < 16; ++j) {
        mx0 = fmaxf(mx0, fmaxf(sacc[j][0], sacc[j][1]));
        mx1 = fmaxf(mx1, fmaxf(sacc[j][2], sacc[j][3]));
    }
    mx0 = fmaxf(mx0, __shfl_xor_sync(~0u, mx0, 1));
    mx0 = fmaxf(mx0, __shfl_xor_sync(~0u, mx0, 2));
    mx1 = fmaxf(mx1, __shfl_xor_sync(~0u, mx1, 1));
    mx1 = fmaxf(mx1, __shfl_xor_sync(~0u, mx1, 2));
    float sum0 = 0.0f, sum1 = 0.0f;
    #pragma unroll
    for (int j = 0; j < 16; ++j) {
        sacc[j][0] = __expf(sacc[j][0] - mx0); sum0 += sacc[j][0];
        sacc[j][1] = __expf(sacc[j][1] - mx0); sum0 += sacc[j][1];
        sacc[j][2] = __expf(sacc[j][2] - mx1); sum1 += sacc[j][2];
        sacc[j][3] = __expf(sacc[j][3] - mx1); sum1 += sacc[j][3];
    }
    sum0 += __shfl_xor_sync(~0u, sum0, 1);
    sum0 += __shfl_xor_sync(~0u, sum0, 2);
    sum1 += __shfl_xor_sync(~0u, sum1, 1);
    sum1 += __shfl_xor_sync(~0u, sum1, 2);
    const float inv0 = 1.0f / sum0, inv1 = 1.0f / sum1;

    uint32_t phi[8][4], plo[8][4];
    #pragma unroll
    for (int kt = 0; kt < 8; ++kt) {
        int j0 = 2 * kt, j1 = 2 * kt + 1;
        float v00 = sacc[j0][0] * inv0, v01 = sacc[j0][1] * inv0;
        float v02 = sacc[j0][2] * inv1, v03 = sacc[j0][3] * inv1;
        float v10 = sacc[j1][0] * inv0, v11 = sacc[j1][1] * inv0;
        float v12 = sacc[j1][2] * inv1, v13 = sacc[j1][3] * inv1;
        phi[kt][0] = pk_hi(v00, v01); plo[kt][0] = pk_lo(v00, v01);
        phi[kt][1] = pk_hi(v02, v03); plo[kt][1] = pk_lo(v02, v03);
        phi[kt][2] = pk_hi(v10, v11); plo[kt][2] = pk_lo(v10, v11);
        phi[kt][3] = pk_hi(v12, v13); plo[kt][3] = pk_lo(v12, v13);
    }

    const float wpv = Wp[0];
    const int g = lane >> 2, t4 = lane & 3;

    for (int cc = 0; cc < 4; ++cc) {
        cp_wait0();
        __syncthreads();
        float oacc[8][4];
        #pragma unroll
        for (int j = 0; j < 8; ++j)
            #pragma unroll
            for (int e = 0; e < 4; ++e) oacc[j][e] = 0.0f;

        #pragma unroll
        for (int kt = 0; kt < 8; ++kt) {
            const int vrow = kt * 16 + (lane & 15);
            #pragma unroll
            for (int vc = 0; vc < 4; ++vc) {
                int c16 = vc * 2 + (lane >> 4);
                uint32_t voff = vrow * 128 + ((c16 ^ (vrow & 7)) << 4);
                uint32_t r0, r1, r2, r3;
                ldm_x4_t(r0, r1, r2, r3, sb + voff);
                mma16816(oacc[2 * vc],     phi[kt], r0, r1);
                mma16816(oacc[2 * vc + 1], phi[kt], r2, r3);
                mma16816(oacc[2 * vc],     plo[kt], r0, r1);
                mma16816(oacc[2 * vc + 1], plo[kt], r2, r3);
                ldm_x4_t(r0, r1, r2, r3, sb + 16384 + voff);
                mma16816(oacc[2 * vc],     phi[kt], r0, r1);
                mma16816(oacc[2 * vc + 1], phi[kt], r2, r3);
            }
        }
        __syncthreads();
        if (cc < 3) { loadV(cc + 1); cp_commit(); }
        #pragma unroll
        for (int j = 0; j < 8; ++j) {
            int col = j * 8 + t4 * 2;
            *(float2*)&Os[(m0 + g) * 66 + col]     = make_float2(oacc[j][0], oacc[j][1]);
            *(float2*)&Os[(m0 + g + 8) * 66 + col] = make_float2(oacc[j][2], oacc[j][3]);
        }
        __syncthreads();
        #pragma unroll
        for (int it = 0; it < 32; ++it) {
            int idx = it * 256 + tid;
            int c = idx >> 7, w = idx & 127;
            size_t gaddr = (((size_t)b * 256 + cc * 64 + c) * 128 + h) * 128 + w;
            out[gaddr] = a[gaddr] + Os[w * 66 + c] * wpv;
        }
        __syncthreads();
    }
}

extern "C" void kernel_launch(void* const* d_in, const int* in_sizes, int n_in,
                              void* d_out, int out_size)
{
    const float* a  = (const float*)d_in[0];
    const float* wq = (const float*)d_in[1];
    const float* bq = (const float*)d_in[2];
    const float* wk = (const float*)d_in[3];
    const float* bk = (const float*)d_in[4];
    const float* wv = (const float*)d_in[5];
    const float* bv = (const float*)d_in[6];
    const float* Wp = (const float*)d_in[7];
    float* out = (float*)d_out;
    (void)in_sizes; (void)n_in; (void)out_size;

    cudaFuncSetAttribute(qkv_mma, cudaFuncAttributeMaxDynamicSharedMemorySize, QKV_SMEM);
    cudaFuncSetAttribute(attn_mma, cudaFuncAttributeMaxDynamicSharedMemorySize, ATTN_SMEM);

    wconvert<<<768, 256>>>(wq, wk, wv);
    xconvert<<<32768, 256>>>(a);
    qkv_mma<<<dim3(6, 1024), 256, QKV_SMEM>>>(bq, bk, bv);
    attn_mma<<<1024, 256, ATTN_SMEM>>>(a, Wp, out);
}

// round 8
// speedup vs baseline: 2.2965x; 2.2965x over previous
#include <cuda_runtime.h>
#include <cuda_fp16.h>
#include <stdint.h>
#include <math.h>

#define B_DIM 8
#define C_DIM 256
#define H_DIM 128
#define W_DIM 128
#define HW    (H_DIM * W_DIM)
#define NTOK  (B_DIM * HW)
#define QK_SCALE 0.0625f

// q/k/v fp16, [token][channel]
__device__ __half g_q[NTOK * C_DIM];
__device__ __half g_k[NTOK * C_DIM];
__device__ __half g_v[NTOK * C_DIM];
// X fp16 c-major: [c][token]
__device__ __half g_x[C_DIM * NTOK];
// Weights fp16: [mat][o][c]
__device__ __half g_w[3 * C_DIM * C_DIM];

__device__ __forceinline__ uint32_t smem_u32(const void* p) {
    uint32_t a;
    asm("{ .reg .u64 t; cvta.to.shared.u64 t, %1; cvt.u32.u64 %0, t; }" : "=r"(a) : "l"(p));
    return a;
}
__device__ __forceinline__ void cp16(uint32_t dst, const void* src) {
    asm volatile("cp.async.cg.shared.global [%0], [%1], 16;" :: "r"(dst), "l"(src));
}
__device__ __forceinline__ void cp_commit() { asm volatile("cp.async.commit_group;" ::: "memory"); }
__device__ __forceinline__ void cp_wait1()  { asm volatile("cp.async.wait_group 1;" ::: "memory"); }
__device__ __forceinline__ void cp_wait0()  { asm volatile("cp.async.wait_group 0;" ::: "memory"); }

__device__ __forceinline__ void ldm_x4(uint32_t& r0, uint32_t& r1, uint32_t& r2, uint32_t& r3, uint32_t addr) {
    asm volatile("ldmatrix.sync.aligned.m8n8.x4.shared.b16 {%0,%1,%2,%3}, [%4];"
                 : "=r"(r0), "=r"(r1), "=r"(r2), "=r"(r3) : "r"(addr));
}
__device__ __forceinline__ void ldm_x4_t(uint32_t& r0, uint32_t& r1, uint32_t& r2, uint32_t& r3, uint32_t addr) {
    asm volatile("ldmatrix.sync.aligned.m8n8.x4.trans.shared.b16 {%0,%1,%2,%3}, [%4];"
                 : "=r"(r0), "=r"(r1), "=r"(r2), "=r"(r3) : "r"(addr));
}
// fp16 MMA, fp32 accumulate
__device__ __forceinline__ void mmaf16(float* c, const uint32_t* a, uint32_t b0, uint32_t b1) {
    asm volatile("mma.sync.aligned.m16n8k16.row.col.f32.f16.f16.f32 "
                 "{%0,%1,%2,%3},{%4,%5,%6,%7},{%8,%9},{%0,%1,%2,%3};"
                 : "+f"(c[0]), "+f"(c[1]), "+f"(c[2]), "+f"(c[3])
                 : "r"(a[0]), "r"(a[1]), "r"(a[2]), "r"(a[3]), "r"(b0), "r"(b1));
}
__device__ __forceinline__ uint32_t pkh(float x, float y) {
    __half2 t = __floats2half2_rn(x, y);
    return *(uint32_t*)&t;
}

__global__ __launch_bounds__(256)
void wconvert(const float* __restrict__ wq, const float* __restrict__ wk,
              const float* __restrict__ wv)
{
    int idx = blockIdx.x * 256 + threadIdx.x;
    int mat = idx >> 16, r = idx & 65535;
    const float* src = (mat == 0) ? wq : (mat == 1) ? wk : wv;
    g_w[idx] = __float2half(src[r]);
}

// a NCHW fp32 -> g_x [c][token] fp16 (coalesced both sides)
__global__ __launch_bounds__(256)
void xconvert(const float* __restrict__ a)
{
    int idx4 = blockIdx.x * 256 + threadIdx.x;
    int b    = idx4 >> 20;
    int rem  = idx4 & 1048575;
    int c    = rem >> 12;
    int hw4  = rem & 4095;
    float4 v = *(const float4*)(a + (size_t)idx4 * 4);
    size_t o = (size_t)c * NTOK + (size_t)b * HW + (size_t)hw4 * 4;
    __half2* ph = (__half2*)(g_x + o);
    ph[0] = __floats2half2_rn(v.x, v.y);
    ph[1] = __floats2half2_rn(v.z, v.w);
}

// ===========================================================================
// QKV GEMM: single-pass fp16, K=256 (4 chunks of 64), double-buffered.
// Grid (6,1024): x = mat*2+half, y = token tile. CTA 128 tok x 128 out.
// A smem [k=64][m=128] fp16 (ldmatrix.trans), B smem [n=128][k=64].
// ===========================================================================
#define QKV_STAGE 32768
#define QKV_SMEM  65536

__global__ __launch_bounds__(256, 2)
void qkv_mma(const float* __restrict__ bq, const float* __restrict__ bk,
             const float* __restrict__ bv)
{
    extern __shared__ char smem[];
    const uint32_t sb = smem_u32(smem);
    const int tid = threadIdx.x, lane = tid & 31, wid = tid >> 5;
    const int wm0 = (wid & 3) * 32;
    const int wn0 = (wid >> 2) * 64;
    const int mat  = blockIdx.x >> 1;
    const int half = blockIdx.x & 1;
    const int tok0 = blockIdx.y * 128;

    const __half* xB = g_x + tok0;
    const __half* wB = g_w + mat * 65536 + half * 32768;

    const int lrowA = tid >> 4, lc16A = tid & 15;
    const int lrowB = tid >> 3, lc16B = tid & 7;

    auto loadIt = [&](int stg, int kc) {
        const uint32_t st = sb + stg * QKV_STAGE;
        const __half* As = xB + (size_t)(kc * 64) * NTOK;
        #pragma unroll
        for (int r = 0; r < 4; ++r) {
            int row = r * 16 + lrowA;
            cp16(st + row * 256 + ((lc16A ^ (row & 7)) << 4),
                 As + (size_t)row * NTOK + lc16A * 8);
        }
        const __half* Bs = wB + kc * 64;
        #pragma unroll
        for (int r = 0; r < 4; ++r) {
            int row = r * 32 + lrowB;
            cp16(st + 16384 + row * 128 + ((lc16B ^ (row & 7)) << 4),
                 Bs + row * 256 + lc16B * 8);
        }
    };

    float acc[2][8][4];
    #pragma unroll
    for (int mt = 0; mt < 2; ++mt)
        #pragma unroll
        for (int n8 = 0; n8 < 8; ++n8)
            #pragma unroll
            for (int e = 0; e < 4; ++e) acc[mt][n8][e] = 0.0f;

    loadIt(0, 0); cp_commit();

    for (int kc = 0; kc < 4; ++kc) {
        if (kc < 3) { loadIt((kc + 1) & 1, kc + 1); cp_commit(); cp_wait1(); }
        else cp_wait0();
        __syncthreads();
        const uint32_t st = sb + (kc & 1) * QKV_STAGE;

        #pragma unroll
        for (int ks = 0; ks < 4; ++ks) {
            uint32_t af[2][4];
            const int arow = ks * 16 + (lane & 7) + ((lane >> 4) << 3);
            #pragma unroll
            for (int mt = 0; mt < 2; ++mt) {
                int chunk = (wm0 >> 3) + mt * 2 + ((lane >> 3) & 1);
                uint32_t addr = st + arow * 256 + ((chunk ^ (arow & 7)) << 4);
                ldm_x4_t(af[mt][0], af[mt][1], af[mt][2], af[mt][3], addr);
            }
            const int rbase = (lane & 7) + ((lane >> 3) & 1) * 8;
            const int c16 = ks * 2 + (lane >> 4);
            #pragma unroll
            for (int ng = 0; ng < 4; ++ng) {
                int brow = wn0 + ng * 16 + rbase;
                uint32_t bsw = brow * 128 + ((c16 ^ (brow & 7)) << 4);
                uint32_t b0, b1, b2, b3;
                ldm_x4(b0, b1, b2, b3, st + 16384 + bsw);
                #pragma unroll
                for (int mt = 0; mt < 2; ++mt) {
                    mmaf16(acc[mt][2 * ng],     af[mt], b0, b2);
                    mmaf16(acc[mt][2 * ng + 1], af[mt], b1, b3);
                }
            }
        }
        __syncthreads();
    }

    const float* bias = (mat == 0) ? bq : (mat == 1) ? bk : bv;
    const float scale = (mat == 0) ? QK_SCALE : 1.0f;
    __half* dst = (mat == 0) ? g_q : (mat == 1) ? g_k : g_v;

    const int g = lane >> 2, t = lane & 3;
    #pragma unroll
    for (int mt = 0; mt < 2; ++mt) {
        size_t r0 = (size_t)(tok0 + wm0 + mt * 16 + g), r1 = r0 + 8;
        #pragma unroll
        for (int n8 = 0; n8 < 8; ++n8) {
            int o = half * 128 + wn0 + n8 * 8 + t * 2;
            float b0v = bias[o], b1v = bias[o + 1];
            *(uint32_t*)(dst + r0 * 256 + o) = pkh((acc[mt][n8][0] + b0v) * scale,
                                                   (acc[mt][n8][1] + b1v) * scale);
            *(uint32_t*)(dst + r1 * 256 + o) = pkh((acc[mt][n8][2] + b0v) * scale,
                                                   (acc[mt][n8][3] + b1v) * scale);
        }
    }
}

// ===========================================================================
// HMMA attention: single-pass fp16. One CTA per scanline, 8 warps x 16 rows.
// S chunk {q 16KB @0, k 16KB @16384}; V chunk 16KB @0; Os fp32 @32768.
// ===========================================================================
#define ATTN_SMEM 66560

__global__ __launch_bounds__(256, 2)
void attn_mma(const float* __restrict__ a, const float* __restrict__ Wp,
              float* __restrict__ out)
{
    extern __shared__ char smem[];
    const uint32_t sb = smem_u32(smem);
    float* Os = (float*)(smem + 32768);
    const int tid = threadIdx.x, lane = tid & 31, wid = tid >> 5;
    const int m0 = wid * 16;
    const int bh = blockIdx.x, b = bh >> 7, h = bh & 127;
    const size_t tokbase = (size_t)bh * 128;

    const int lrow = tid >> 3, lc16 = tid & 7;

    auto loadQK = [&](int kc) {
        const size_t scol = tokbase * 256 + kc * 64;
        #pragma unroll
        for (int r = 0; r < 4; ++r) {
            int row = r * 32 + lrow;
            uint32_t doff = row * 128 + ((lc16 ^ (row & 7)) << 4);
            size_t soff = scol + (size_t)row * 256 + lc16 * 8;
            cp16(sb + 0     + doff, g_q + soff);
            cp16(sb + 16384 + doff, g_k + soff);
        }
    };
    auto loadV = [&](int cc) {
        const size_t scol = tokbase * 256 + cc * 64;
        #pragma unroll
        for (int r = 0; r < 4; ++r) {
            int row = r * 32 + lrow;
            uint32_t doff = row * 128 + ((lc16 ^ (row & 7)) << 4);
            cp16(sb + doff, g_v + scol + (size_t)row * 256 + lc16 * 8);
        }
    };

    float sacc[16][4];
    #pragma unroll
    for (int j = 0; j < 16; ++j)
        #pragma unroll
        for (int e = 0; e < 4; ++e) sacc[j][e] = 0.0f;

    loadQK(0); cp_commit();
    for (int kc = 0; kc < 4; ++kc) {
        cp_wait0();
        __syncthreads();
        #pragma unroll
        for (int ks = 0; ks < 4; ++ks) {
            uint32_t ah[4];
            const int c16 = ks * 2 + (lane >> 4);
            int arow = m0 + (lane & 15);
            uint32_t aoff = arow * 128 + ((c16 ^ (arow & 7)) << 4);
            ldm_x4(ah[0], ah[1], ah[2], ah[3], sb + aoff);
            #pragma unroll
            for (int bn = 0; bn < 8; ++bn) {
                int brow = bn * 16 + (lane & 15);
                uint32_t boff = brow * 128 + ((c16 ^ (brow & 7)) << 4);
                uint32_t b0, b1, b2, b3;
                ldm_x4(b0, b1, b2, b3, sb + 16384 + boff);
                mmaf16(sacc[2 * bn],     ah, b0, b2);
                mmaf16(sacc[2 * bn + 1], ah, b1, b3);
            }
        }
        __syncthreads();
        if (kc < 3) { loadQK(kc + 1); cp_commit(); }
    }
    loadV(0); cp_commit();

    float mx0 = -1e30f, mx1 = -1e30f;
    #pragma unroll
    for (int j = 0; j < 16; ++j) {
        mx0 = fmaxf(mx0, fmaxf(sacc[j][0], sacc[j][1]));
        mx1 = fmaxf(mx1, fmaxf(sacc[j][2], sacc[j][3]));
    }
    mx0 = fmaxf(mx0, __shfl_xor_sync(~0u, mx0, 1));
    mx0 = fmaxf(mx0, __shfl_xor_sync(~0u, mx0, 2));
    mx1 = fmaxf(mx1, __shfl_xor_sync(~0u, mx1, 1));
    mx1 = fmaxf(mx1, __shfl_xor_sync(~0u, mx1, 2));
    float sum0 = 0.0f, sum1 = 0.0f;
    #pragma unroll
    for (int j = 0; j < 16; ++j) {
        sacc[j][0] = __expf(sacc[j][0] - mx0); sum0 += sacc[j][0];
        sacc[j][1] = __expf(sacc[j][1] - mx0); sum0 += sacc[j][1];
        sacc[j][2] = __expf(sacc[j][2] - mx1); sum1 += sacc[j][2];
        sacc[j][3] = __expf(sacc[j][3] - mx1); sum1 += sacc[j][3];
    }
    sum0 += __shfl_xor_sync(~0u, sum0, 1);
    sum0 += __shfl_xor_sync(~0u, sum0, 2);
    sum1 += __shfl_xor_sync(~0u, sum1, 1);
    sum1 += __shfl_xor_sync(~0u, sum1, 2);
    const float inv0 = 1.0f / sum0, inv1 = 1.0f / sum1;

    uint32_t phi[8][4];
    #pragma unroll
    for (int kt = 0; kt < 8; ++kt) {
        int j0 = 2 * kt, j1 = 2 * kt + 1;
        phi[kt][0] = pkh(sacc[j0][0] * inv0, sacc[j0][1] * inv0);
        phi[kt][1] = pkh(sacc[j0][2] * inv1, sacc[j0][3] * inv1);
        phi[kt][2] = pkh(sacc[j1][0] * inv0, sacc[j1][1] * inv0);
        phi[kt][3] = pkh(sacc[j1][2] * inv1, sacc[j1][3] * inv1);
    }

    const float wpv = Wp[0];
    const int g = lane >> 2, t4 = lane & 3;

    for (int cc = 0; cc < 4; ++cc) {
        cp_wait0();
        __syncthreads();
        float oacc[8][4];
        #pragma unroll
        for (int j = 0; j < 8; ++j)
            #pragma unroll
            for (int e = 0; e < 4; ++e) oacc[j][e] = 0.0f;

        #pragma unroll
        for (int kt = 0; kt < 8; ++kt) {
            const int vrow = kt * 16 + (lane & 15);
            #pragma unroll
            for (int vc = 0; vc < 4; ++vc) {
                int c16 = vc * 2 + (lane >> 4);
                uint32_t voff = vrow * 128 + ((c16 ^ (vrow & 7)) << 4);
                uint32_t r0, r1, r2, r3;
                ldm_x4_t(r0, r1, r2, r3, sb + voff);
                mmaf16(oacc[2 * vc],     phi[kt], r0, r1);
                mmaf16(oacc[2 * vc + 1], phi[kt], r2, r3);
            }
        }
        __syncthreads();
        if (cc < 3) { loadV(cc + 1); cp_commit(); }
        #pragma unroll
        for (int j = 0; j < 8; ++j) {
            int col = j * 8 + t4 * 2;
            *(float2*)&Os[(m0 + g) * 66 + col]     = make_float2(oacc[j][0], oacc[j][1]);
            *(float2*)&Os[(m0 + g + 8) * 66 + col] = make_float2(oacc[j][2], oacc[j][3]);
        }
        __syncthreads();
        #pragma unroll
        for (int it = 0; it < 32; ++it) {
            int idx = it * 256 + tid;
            int c = idx >> 7, w = idx & 127;
            size_t gaddr = (((size_t)b * 256 + cc * 64 + c) * 128 + h) * 128 + w;
            out[gaddr] = a[gaddr] + Os[w * 66 + c] * wpv;
        }
        __syncthreads();
    }
}

extern "C" void kernel_launch(void* const* d_in, const int* in_sizes, int n_in,
                              void* d_out, int out_size)
{
    const float* a  = (const float*)d_in[0];
    const float* wq = (const float*)d_in[1];
    const float* bq = (const float*)d_in[2];
    const float* wk = (const float*)d_in[3];
    const float* bk = (const float*)d_in[4];
    const float* wv = (const float*)d_in[5];
    const float* bv = (const float*)d_in[6];
    const float* Wp = (const float*)d_in[7];
    float* out = (float*)d_out;
    (void)in_sizes; (void)n_in; (void)out_size;

    cudaFuncSetAttribute(qkv_mma, cudaFuncAttributeMaxDynamicSharedMemorySize, QKV_SMEM);
    cudaFuncSetAttribute(attn_mma, cudaFuncAttributeMaxDynamicSharedMemorySize, ATTN_SMEM);

    wconvert<<<768, 256>>>(wq, wk, wv);
    xconvert<<<32768, 256>>>(a);
    qkv_mma<<<dim3(6, 1024), 256, QKV_SMEM>>>(bq, bk, bv);
    attn_mma<<<1024, 256, ATTN_SMEM>>>(a, Wp, out);
}

// round 12
// speedup vs baseline: 2.5078x; 1.0920x over previous
#include <cuda_runtime.h>
#include <cuda_fp16.h>
#include <stdint.h>
#include <math.h>

#define B_DIM 8
#define C_DIM 256
#define H_DIM 128
#define W_DIM 128
#define HW    (H_DIM * W_DIM)
#define NTOK  (B_DIM * HW)
#define QK_SCALE 0.0625f

// X fp16 c-major: [c][token]
__device__ __half g_x[C_DIM * NTOK];
// T = X*M and V = X*Wv + bv, fp16 [token][channel]
__device__ __half g_t[NTOK * C_DIM];
__device__ __half g_v[NTOK * C_DIM];
// Wv fp16 [o][c]; Mt[c'][c] = scale * sum_o Wq[o,c] Wk[o,c'] fp16; u fp32
__device__ __half g_wv[C_DIM * C_DIM];
__device__ __half g_mt[C_DIM * C_DIM];
__device__ float  g_u[C_DIM];

__device__ __forceinline__ uint32_t smem_u32(const void* p) {
    uint32_t a;
    asm("{ .reg .u64 t; cvta.to.shared.u64 t, %1; cvt.u32.u64 %0, t; }" : "=r"(a) : "l"(p));
    return a;
}
__device__ __forceinline__ void cp16(uint32_t dst, const void* src) {
    asm volatile("cp.async.cg.shared.global [%0], [%1], 16;" :: "r"(dst), "l"(src));
}
__device__ __forceinline__ void cp_commit() { asm volatile("cp.async.commit_group;" ::: "memory"); }
__device__ __forceinline__ void cp_wait1()  { asm volatile("cp.async.wait_group 1;" ::: "memory"); }
__device__ __forceinline__ void cp_wait0()  { asm volatile("cp.async.wait_group 0;" ::: "memory"); }

__device__ __forceinline__ void ldm_x4(uint32_t& r0, uint32_t& r1, uint32_t& r2, uint32_t& r3, uint32_t addr) {
    asm volatile("ldmatrix.sync.aligned.m8n8.x4.shared.b16 {%0,%1,%2,%3}, [%4];"
                 : "=r"(r0), "=r"(r1), "=r"(r2), "=r"(r3) : "r"(addr));
}
__device__ __forceinline__ void ldm_x4_t(uint32_t& r0, uint32_t& r1, uint32_t& r2, uint32_t& r3, uint32_t addr) {
    asm volatile("ldmatrix.sync.aligned.m8n8.x4.trans.shared.b16 {%0,%1,%2,%3}, [%4];"
                 : "=r"(r0), "=r"(r1), "=r"(r2), "=r"(r3) : "r"(addr));
}
__device__ __forceinline__ void mmaf16(float* c, const uint32_t* a, uint32_t b0, uint32_t b1) {
    asm volatile("mma.sync.aligned.m16n8k16.row.col.f32.f16.f16.f32 "
                 "{%0,%1,%2,%3},{%4,%5,%6,%7},{%8,%9},{%0,%1,%2,%3};"
                 : "+f"(c[0]), "+f"(c[1]), "+f"(c[2]), "+f"(c[3])
                 : "r"(a[0]), "r"(a[1]), "r"(a[2]), "r"(a[3]), "r"(b0), "r"(b1));
}
__device__ __forceinline__ uint32_t pkh(float x, float y) {
    __half2 t = __floats2half2_rn(x, y);
    return *(uint32_t*)&t;
}

// Wv fp32 -> fp16
__global__ __launch_bounds__(256)
void wvconvert(const float* __restrict__ wv)
{
    int idx = blockIdx.x * 256 + threadIdx.x;
    g_wv[idx] = __float2half(wv[idx]);
}

// Mt[c'][c] = scale * sum_o Wq[o,c]*Wk[o,c'];  u[c] = scale * sum_o bq[o]*Wk[o,c]
__global__ __launch_bounds__(256)
void mconvert(const float* __restrict__ wq, const float* __restrict__ wk,
              const float* __restrict__ bq)
{
    int cp = blockIdx.x;       // 0..255 => Mt row c'; 256 => u
    int c  = threadIdx.x;
    if (cp < 256) {
        float acc = 0.0f;
        for (int o = 0; o < 256; ++o)
            acc += wq[o * 256 + c] * wk[o * 256 + cp];
        g_mt[cp * 256 + c] = __float2half(acc * QK_SCALE);
    } else {
        float acc = 0.0f;
        for (int o = 0; o < 256; ++o)
            acc += bq[o] * wk[o * 256 + c];
        g_u[c] = acc * QK_SCALE;
    }
}

// a NCHW fp32 -> g_x [c][token] fp16 (coalesced both sides)
__global__ __launch_bounds__(256)
void xconvert(const float* __restrict__ a)
{
    int idx4 = blockIdx.x * 256 + threadIdx.x;
    int b    = idx4 >> 20;
    int rem  = idx4 & 1048575;
    int c    = rem >> 12;
    int hw4  = rem & 4095;
    float4 v = *(const float4*)(a + (size_t)idx4 * 4);
    size_t o = (size_t)c * NTOK + (size_t)b * HW + (size_t)hw4 * 4;
    __half2* ph = (__half2*)(g_x + o);
    ph[0] = __floats2half2_rn(v.x, v.y);
    ph[1] = __floats2half2_rn(v.z, v.w);
}

// ===========================================================================
// T/V GEMM: grid (4,1024). variant: 0,1 = T halves (B=Mt); 2,3 = V halves
// (B=Wv, +bv). CTA 128 tok x 128 out, K=256, double-buffered.
// ===========================================================================
#define TV_STAGE 32768
#define TV_SMEM  65536

__global__ __launch_bounds__(256, 2)
void tv_mma(const float* __restrict__ bv)
{
    extern __shared__ char smem[];
    const uint32_t sb = smem_u32(smem);
    const int tid = threadIdx.x, lane = tid & 31, wid = tid >> 5;
    const int wm0 = (wid & 3) * 32;
    const int wn0 = (wid >> 2) * 64;
    const int variant = blockIdx.x;
    const int half = variant & 1;
    const int isV  = variant >> 1;
    const int tok0 = blockIdx.y * 128;

    const __half* xB = g_x + tok0;
    const __half* wB = (isV ? g_wv : g_mt) + half * 128 * 256;

    const int lrowA = tid >> 4, lc16A = tid & 15;
    const int lrowB = tid >> 3, lc16B = tid & 7;

    auto loadIt = [&](int stg, int kc) {
        const uint32_t st = sb + stg * TV_STAGE;
        const __half* As = xB + (size_t)(kc * 64) * NTOK;
        #pragma unroll
        for (int r = 0; r < 4; ++r) {
            int row = r * 16 + lrowA;
            cp16(st + row * 256 + ((lc16A ^ (row & 7)) << 4),
                 As + (size_t)row * NTOK + lc16A * 8);
        }
        const __half* Bs = wB + kc * 64;
        #pragma unroll
        for (int r = 0; r < 4; ++r) {
            int row = r * 32 + lrowB;
            cp16(st + 16384 + row * 128 + ((lc16B ^ (row & 7)) << 4),
                 Bs + row * 256 + lc16B * 8);
        }
    };

    float acc[2][8][4];
    #pragma unroll
    for (int mt = 0; mt < 2; ++mt)
        #pragma unroll
        for (int n8 = 0; n8 < 8; ++n8)
            #pragma unroll
            for (int e = 0; e < 4; ++e) acc[mt][n8][e] = 0.0f;

    loadIt(0, 0); cp_commit();

    for (int kc = 0; kc < 4; ++kc) {
        if (kc < 3) { loadIt((kc + 1) & 1, kc + 1); cp_commit(); cp_wait1(); }
        else cp_wait0();
        __syncthreads();
        const uint32_t st = sb + (kc & 1) * TV_STAGE;

        #pragma unroll
        for (int ks = 0; ks < 4; ++ks) {
            uint32_t af[2][4];
            const int arow = ks * 16 + (lane & 7) + ((lane >> 4) << 3);
            #pragma unroll
            for (int mt = 0; mt < 2; ++mt) {
                int chunk = (wm0 >> 3) + mt * 2 + ((lane >> 3) & 1);
                uint32_t addr = st + arow * 256 + ((chunk ^ (arow & 7)) << 4);
                ldm_x4_t(af[mt][0], af[mt][1], af[mt][2], af[mt][3], addr);
            }
            const int rbase = (lane & 7) + ((lane >> 3) & 1) * 8;
            const int c16 = ks * 2 + (lane >> 4);
            #pragma unroll
            for (int ng = 0; ng < 4; ++ng) {
                int brow = wn0 + ng * 16 + rbase;
                uint32_t bsw = brow * 128 + ((c16 ^ (brow & 7)) << 4);
                uint32_t b0, b1, b2, b3;
                ldm_x4(b0, b1, b2, b3, st + 16384 + bsw);
                #pragma unroll
                for (int mt = 0; mt < 2; ++mt) {
                    mmaf16(acc[mt][2 * ng],     af[mt], b0, b2);
                    mmaf16(acc[mt][2 * ng + 1], af[mt], b1, b3);
                }
            }
        }
        __syncthreads();
    }

    __half* dst = isV ? g_v : g_t;
    const int g = lane >> 2, t = lane & 3;
    #pragma unroll
    for (int mt = 0; mt < 2; ++mt) {
        size_t r0 = (size_t)(tok0 + wm0 + mt * 16 + g), r1 = r0 + 8;
        #pragma unroll
        for (int n8 = 0; n8 < 8; ++n8) {
            int o = half * 128 + wn0 + n8 * 8 + t * 2;
            float b0v = isV ? bv[o] : 0.0f;
            float b1v = isV ? bv[o + 1] : 0.0f;
            *(uint32_t*)(dst + r0 * 256 + o) = pkh(acc[mt][n8][0] + b0v, acc[mt][n8][1] + b1v);
            *(uint32_t*)(dst + r1 * 256 + o) = pkh(acc[mt][n8][2] + b0v, acc[mt][n8][3] + b1v);
        }
    }
}

// ===========================================================================
// Attention: S = T * X^T + gamma, softmax, O = P * V. One CTA per scanline.
// Double-buffered stages 2x32KB {T 16KB, X 16KB}; V reuses stages (16KB each);
// Os fp32 @65536; gamma @99328.
// ===========================================================================
#define ATTN_SMEM 99840

__global__ __launch_bounds__(256, 2)
void attn_mma(const float* __restrict__ a, const float* __restrict__ Wp,
              float* __restrict__ out)
{
    extern __shared__ char smem[];
    const uint32_t sb = smem_u32(smem);
    float* Os  = (float*)(smem + 65536);
    float* gam = (float*)(smem + 99328);
    const int tid = threadIdx.x, lane = tid & 31, wid = tid >> 5;
    const int m0 = wid * 16;
    const int bh = blockIdx.x, b = bh >> 7, h = bh & 127;
    const int tok0 = bh * 128;
    const size_t tokbase = (size_t)bh * 128;

    const int lrow = tid >> 3, lc16 = tid & 7;     // T/V tiles: 128 rows x 8 c16
    const int lrowX = tid >> 4, lc16X = tid & 15;  // X tiles: 64 rows x 16 c16

    auto loadTX = [&](int stg, int kc) {
        const uint32_t st = sb + stg * 32768;
        const size_t scol = tokbase * 256 + kc * 64;
        #pragma unroll
        for (int r = 0; r < 4; ++r) {
            int row = r * 32 + lrow;
            uint32_t doff = row * 128 + ((lc16 ^ (row & 7)) << 4);
            cp16(st + doff, g_t + scol + (size_t)row * 256 + lc16 * 8);
        }
        #pragma unroll
        for (int r = 0; r < 4; ++r) {
            int row = r * 16 + lrowX;      // c-row within chunk
            uint32_t doff = row * 256 + ((lc16X ^ (row & 7)) << 4);
            cp16(st + 16384 + doff,
                 g_x + (size_t)(kc * 64 + row) * NTOK + tok0 + lc16X * 8);
        }
    };
    auto loadV = [&](int stg, int cc) {
        const uint32_t st = sb + stg * 32768;
        const size_t scol = tokbase * 256 + cc * 64;
        #pragma unroll
        for (int r = 0; r < 4; ++r) {
            int row = r * 32 + lrow;
            uint32_t doff = row * 128 + ((lc16 ^ (row & 7)) << 4);
            cp16(st + doff, g_v + scol + (size_t)row * 256 + lc16 * 8);
        }
    };

    float sacc[16][4];
    #pragma unroll
    for (int j = 0; j < 16; ++j)
        #pragma unroll
        for (int e = 0; e < 4; ++e) sacc[j][e] = 0.0f;

    float greg = 0.0f;   // per-thread gamma accumulator (threads < 128)

    loadTX(0, 0); cp_commit();
    for (int kc = 0; kc < 4; ++kc) {
        if (kc < 3) { loadTX((kc + 1) & 1, kc + 1); cp_commit(); cp_wait1(); }
        else cp_wait0();
        __syncthreads();
        const uint32_t st = sb + (kc & 1) * 32768;
        #pragma unroll
        for (int ks = 0; ks < 4; ++ks) {
            uint32_t ah[4];
            const int c16 = ks * 2 + (lane >> 4);
            int arow = m0 + (lane & 15);
            uint32_t aoff = arow * 128 + ((c16 ^ (arow & 7)) << 4);
            ldm_x4(ah[0], ah[1], ah[2], ah[3], st + aoff);
            const int brow = ks * 16 + (lane & 15);
            #pragma unroll
            for (int bn = 0; bn < 8; ++bn) {
                int nchunk = bn * 2 + (lane >> 4);
                uint32_t boff = brow * 256 + ((nchunk ^ (brow & 7)) << 4);
                uint32_t b0, b1, b2, b3;
                ldm_x4_t(b0, b1, b2, b3, st + 16384 + boff);
                // trans-load register order: (b0,b1) = k-halves of even n-octet,
                // (b2,b3) = k-halves of odd n-octet (matches validated PV pattern)
                mmaf16(sacc[2 * bn],     ah, b0, b1);
                mmaf16(sacc[2 * bn + 1], ah, b2, b3);
            }
        }
        // gamma partial: gam[n] += sum_c X[c][n] * u[kc*64+c]
        if (tid < 128) {
            #pragma unroll 8
            for (int c = 0; c < 64; ++c) {
                uint32_t xoff = st + 16384 + c * 256
                              + (((tid >> 3) ^ (c & 7)) << 4) + (tid & 7) * 2;
                float xv = __half2float(*(const __half*)(smem + (xoff - sb)));
                greg += xv * __ldg(&g_u[kc * 64 + c]);
            }
        }
        __syncthreads();
    }
    loadV(0, 0); cp_commit();
    if (tid < 128) gam[tid] = greg;
    __syncthreads();

    const int g = lane >> 2, t4 = lane & 3;
    // add gamma (per key column), then softmax
    #pragma unroll
    for (int j = 0; j < 16; ++j) {
        float ga = gam[j * 8 + t4 * 2], gb = gam[j * 8 + t4 * 2 + 1];
        sacc[j][0] += ga; sacc[j][1] += gb;
        sacc[j][2] += ga; sacc[j][3] += gb;
    }

    float mx0 = -1e30f, mx1 = -1e30f;
    #pragma unroll
    for (int j = 0; j < 16; ++j) {
        mx0 = fmaxf(mx0, fmaxf(sacc[j][0], sacc[j][1]));
        mx1 = fmaxf(mx1, fmaxf(sacc[j][2], sacc[j][3]));
    }
    mx0 = fmaxf(mx0, __shfl_xor_sync(~0u, mx0, 1));
    mx0 = fmaxf(mx0, __shfl_xor_sync(~0u, mx0, 2));
    mx1 = fmaxf(mx1, __shfl_xor_sync(~0u, mx1, 1));
    mx1 = fmaxf(mx1, __shfl_xor_sync(~0u, mx1, 2));
    float sum0 = 0.0f, sum1 = 0.0f;
    #pragma unroll
    for (int j = 0; j < 16; ++j) {
        sacc[j][0] = __expf(sacc[j][0] - mx0); sum0 += sacc[j][0];
        sacc[j][1] = __expf(sacc[j][1] - mx0); sum0 += sacc[j][1];
        sacc[j][2] = __expf(sacc[j][2] - mx1); sum1 += sacc[j][2];
        sacc[j][3] = __expf(sacc[j][3] - mx1); sum1 += sacc[j][3];
    }
    sum0 += __shfl_xor_sync(~0u, sum0, 1);
    sum0 += __shfl_xor_sync(~0u, sum0, 2);
    sum1 += __shfl_xor_sync(~0u, sum1, 1);
    sum1 += __shfl_xor_sync(~0u, sum1, 2);
    const float inv0 = 1.0f / sum0, inv1 = 1.0f / sum1;

    uint32_t phi[8][4];
    #pragma unroll
    for (int kt = 0; kt < 8; ++kt) {
        int j0 = 2 * kt, j1 = 2 * kt + 1;
        phi[kt][0] = pkh(sacc[j0][0] * inv0, sacc[j0][1] * inv0);
        phi[kt][1] = pkh(sacc[j0][2] * inv1, sacc[j0][3] * inv1);
        phi[kt][2] = pkh(sacc[j1][0] * inv0, sacc[j1][1] * inv0);
        phi[kt][3] = pkh(sacc[j1][2] * inv1, sacc[j1][3] * inv1);
    }

    const float wpv = Wp[0];

    for (int cc = 0; cc < 4; ++cc) {
        if (cc < 3) { loadV((cc + 1) & 1, cc + 1); cp_commit(); cp_wait1(); }
        else cp_wait0();
        __syncthreads();
        const uint32_t vs = sb + (cc & 1) * 32768;
        float oacc[8][4];
        #pragma unroll
        for (int j = 0; j < 8; ++j)
            #pragma unroll
            for (int e = 0; e < 4; ++e) oacc[j][e] = 0.0f;

        #pragma unroll
        for (int kt = 0; kt < 8; ++kt) {
            const int vrow = kt * 16 + (lane & 15);
            #pragma unroll
            for (int vc = 0; vc < 4; ++vc) {
                int c16 = vc * 2 + (lane >> 4);
                uint32_t voff = vrow * 128 + ((c16 ^ (vrow & 7)) << 4);
                uint32_t r0, r1, r2, r3;
                ldm_x4_t(r0, r1, r2, r3, vs + voff);
                mmaf16(oacc[2 * vc],     phi[kt], r0, r1);
                mmaf16(oacc[2 * vc + 1], phi[kt], r2, r3);
            }
        }
        __syncthreads();
        #pragma unroll
        for (int j = 0; j < 8; ++j) {
            int col = j * 8 + t4 * 2;
            *(float2*)&Os[(m0 + g) * 66 + col]     = make_float2(oacc[j][0], oacc[j][1]);
            *(float2*)&Os[(m0 + g + 8) * 66 + col] = make_float2(oacc[j][2], oacc[j][3]);
        }
        __syncthreads();
        #pragma unroll
        for (int it = 0; it < 32; ++it) {
            int idx = it * 256 + tid;
            int c = idx >> 7, w = idx & 127;
            size_t gaddr = (((size_t)b * 256 + cc * 64 + c) * 128 + h) * 128 + w;
            out[gaddr] = a[gaddr] + Os[w * 66 + c] * wpv;
        }
        __syncthreads();
    }
}

extern "C" void kernel_launch(void* const* d_in, const int* in_sizes, int n_in,
                              void* d_out, int out_size)
{
    const float* a  = (const float*)d_in[0];
    const float* wq = (const float*)d_in[1];
    const float* bq = (const float*)d_in[2];
    const float* wk = (const float*)d_in[3];
    const float* bk = (const float*)d_in[4];
    const float* wv = (const float*)d_in[5];
    const float* bv = (const float*)d_in[6];
    const float* Wp = (const float*)d_in[7];
    float* out = (float*)d_out;
    (void)in_sizes; (void)n_in; (void)out_size; (void)bk;

    cudaFuncSetAttribute(tv_mma,   cudaFuncAttributeMaxDynamicSharedMemorySize, TV_SMEM);
    cudaFuncSetAttribute(attn_mma, cudaFuncAttributeMaxDynamicSharedMemorySize, ATTN_SMEM);

    wvconvert<<<256, 256>>>(wv);
    mconvert<<<257, 256>>>(wq, wk, bq);
    xconvert<<<32768, 256>>>(a);
    tv_mma<<<dim3(4, 1024), 256, TV_SMEM>>>(bv);
    attn_mma<<<1024, 256, ATTN_SMEM>>>(a, Wp, out);
}